// round 7
// baseline (speedup 1.0000x reference)
#include <cuda_runtime.h>
#include <cuda_bf16.h>
#include <cstdint>

#define Bb  8
#define Ss  2048
#define Dd  256
#define DOo 256
#define Ll  8
#define Ee  32768

// ---- static device scratch ----
__device__ float g_y[(size_t)Bb * Ll * Ss * DOo];                     // 128 MiB
__device__ __align__(128) __nv_bfloat16 g_xh[(size_t)Bb * Ss * Dd];   // 8 MiB
__device__ __align__(128) __nv_bfloat16 g_xl[(size_t)Bb * Ss * Dd];   // 8 MiB
__device__ __align__(128) __nv_bfloat16 g_wh[(size_t)Ll * DOo * Dd];  // 1 MiB [l][n][k]
__device__ __align__(128) __nv_bfloat16 g_wl[(size_t)Ll * DOo * Dd];  // 1 MiB
__device__ int g_deg[Bb * Ss];
__device__ int g_offs[Bb * Ss + 1];
__device__ int g_cursor[Bb * Ss];
__device__ int g_perm[Bb * Ee];                                       // l*Ss + s

// ---- streams + events, created once at process init (outside capture) ----
static cudaStream_t g_s2 = nullptr;
static cudaEvent_t g_ev0 = nullptr, g_ev1 = nullptr;
static cudaEvent_t g_evG[Bb];
static bool g_streams_ok = false;
namespace {
struct _StreamInit {
    _StreamInit() {
        bool ok = true;
        ok &= (cudaStreamCreateWithFlags(&g_s2, cudaStreamNonBlocking) == cudaSuccess);
        ok &= (cudaEventCreateWithFlags(&g_ev0, cudaEventDisableTiming) == cudaSuccess);
        ok &= (cudaEventCreateWithFlags(&g_ev1, cudaEventDisableTiming) == cudaSuccess);
        for (int i = 0; i < Bb; i++)
            ok &= (cudaEventCreateWithFlags(&g_evG[i], cudaEventDisableTiming) == cudaSuccess);
        g_streams_ok = ok;
    }
} _stream_init;
}

// ================= CSR-build kernels =================
__global__ void k_zero_deg() {
    int i = blockIdx.x * blockDim.x + threadIdx.x;
    if (i < Bb * Ss) g_deg[i] = 0;
}
__global__ void k_hist(const int* __restrict__ tgt) {
    int i = blockIdx.x * blockDim.x + threadIdx.x;
    if (i < Bb * Ee) {
        int b = i / Ee;
        atomicAdd(&g_deg[b * Ss + tgt[i]], 1);
    }
}
__global__ void k_scan() {   // 1024 threads, 16 rows each
    const int t = threadIdx.x;
    const int base = t * 16;
    int loc[16]; int sum = 0;
#pragma unroll
    for (int i = 0; i < 16; i++) { loc[i] = sum; sum += g_deg[base + i]; }
    int lane = t & 31, warp = t >> 5;
    int v = sum;
#pragma unroll
    for (int o = 1; o < 32; o <<= 1) {
        int u = __shfl_up_sync(0xFFFFFFFF, v, o);
        if (lane >= o) v += u;
    }
    __shared__ int wsum[32];
    if (lane == 31) wsum[warp] = v;
    __syncthreads();
    if (warp == 0) {
        int w = wsum[lane];
#pragma unroll
        for (int o = 1; o < 32; o <<= 1) {
            int u = __shfl_up_sync(0xFFFFFFFF, w, o);
            if (lane >= o) w += u;
        }
        wsum[lane] = w;
    }
    __syncthreads();
    int pre = v - sum + (warp ? wsum[warp - 1] : 0);
#pragma unroll
    for (int i = 0; i < 16; i++) {
        int o = pre + loc[i];
        g_offs[base + i]   = o;
        g_cursor[base + i] = o;
    }
    if (t == 1023) g_offs[Bb * Ss] = wsum[31];
}
__global__ void k_fill(const int* __restrict__ tgt, const int* __restrict__ lab,
                       const int* __restrict__ src) {
    int i = blockIdx.x * blockDim.x + threadIdx.x;
    if (i < Bb * Ee) {
        int b = i / Ee;
        int pos = atomicAdd(&g_cursor[b * Ss + tgt[i]], 1);
        g_perm[pos] = lab[i] * Ss + src[i];
    }
}

// ================= prep: split X + split W into bf16 hi/lo =================
__global__ void k_prep(const float* __restrict__ X, const float* __restrict__ W) {
    int i = blockIdx.x * blockDim.x + threadIdx.x;
    if (i < Bb * Ss * Dd) {
        float v = X[i];
        __nv_bfloat16 h = __float2bfloat16(v);
        g_xh[i] = h;
        g_xl[i] = __float2bfloat16(v - __bfloat162float(h));
    }
    if (i < Ll * Dd * DOo) {
        int l = i / (Dd * DOo);
        int r = i - l * (Dd * DOo);
        int k = r >> 8;
        int n = r & 255;
        float v = W[i];
        __nv_bfloat16 h = __float2bfloat16(v);
        size_t o = ((size_t)l * DOo + n) * Dd + k;
        g_wh[o] = h;
        g_wl[o] = __float2bfloat16(v - __bfloat162float(h));
    }
}

// ================= bf16x3 mma.sync GEMM (per-batch) =================
__device__ __forceinline__ uint32_t s2u(const void* p) {
    uint32_t a;
    asm("{ .reg .u64 t; cvta.to.shared.u64 t, %1; cvt.u32.u64 %0, t; }" : "=r"(a) : "l"(p));
    return a;
}
__device__ __forceinline__ void cp16(uint32_t sa, const void* ga) {
    asm volatile("cp.async.cg.shared.global [%0], [%1], 16;" :: "r"(sa), "l"(ga));
}
__device__ __forceinline__ void ldmx4(uint32_t* r, uint32_t addr) {
    asm volatile("ldmatrix.sync.aligned.m8n8.x4.shared.b16 {%0,%1,%2,%3}, [%4];"
                 : "=r"(r[0]), "=r"(r[1]), "=r"(r[2]), "=r"(r[3]) : "r"(addr));
}
__device__ __forceinline__ void mma16816(float* c, const uint32_t* a,
                                         uint32_t b0, uint32_t b1) {
    asm volatile(
        "mma.sync.aligned.m16n8k16.row.col.f32.bf16.bf16.f32 "
        "{%0,%1,%2,%3}, {%4,%5,%6,%7}, {%8,%9}, {%0,%1,%2,%3};"
        : "+f"(c[0]), "+f"(c[1]), "+f"(c[2]), "+f"(c[3])
        : "r"(a[0]), "r"(a[1]), "r"(a[2]), "r"(a[3]), "r"(b0), "r"(b1));
}

#define STAGE_BYTES 32768      // 4 tiles x 8KB (Ah, Al, Bh, Bl), 128 rows x 64B each
#define OFF_AH 0
#define OFF_AL 8192
#define OFF_BH 16384
#define OFF_BL 24576

__global__ __launch_bounds__(256, 2) void k_gemm_mma(const float* __restrict__ bias,
                                                     int bconst) {
    extern __shared__ char smem[];
    const uint32_t sbase = s2u(smem);          // 3 stages x 32KB

    const int tid = threadIdx.x;
    const int lane = tid & 31;
    const int wid = tid >> 5;
    const int warp_m = wid & 1;                // 2 x 64 rows
    const int warp_n = wid >> 1;               // 4 x 32 cols
    const int l = blockIdx.z;                  // label
    const int bl = bconst * Ll + l;
    const int m0 = blockIdx.x * 128;
    const int n0 = blockIdx.y * 128;

    const __nv_bfloat16* Agh = g_xh + ((size_t)(bconst * Ss) + m0) * Dd;
    const __nv_bfloat16* Agl = g_xl + ((size_t)(bconst * Ss) + m0) * Dd;
    const __nv_bfloat16* Bgh = g_wh + ((size_t)l * DOo + n0) * Dd;
    const __nv_bfloat16* Bgl = g_wl + ((size_t)l * DOo + n0) * Dd;

    const int u_row0 = tid >> 2,          u_u0 = tid & 3;
    const int u_row1 = (tid + 256) >> 2,  u_u1 = (tid + 256) & 3;
    const uint32_t so0 = (uint32_t)(u_row0 * 64 + ((u_u0 ^ ((u_row0 >> 1) & 3)) << 4));
    const uint32_t so1 = (uint32_t)(u_row1 * 64 + ((u_u1 ^ ((u_row1 >> 1) & 3)) << 4));

#define LOAD_STAGE(st, it) do {                                                     \
    int koff = (it) * 32;                                                           \
    uint32_t s0 = sbase + (st) * STAGE_BYTES;                                       \
    cp16(s0 + OFF_AH + so0, Agh + (size_t)u_row0 * Dd + koff + u_u0 * 8);           \
    cp16(s0 + OFF_AH + so1, Agh + (size_t)u_row1 * Dd + koff + u_u1 * 8);           \
    cp16(s0 + OFF_AL + so0, Agl + (size_t)u_row0 * Dd + koff + u_u0 * 8);           \
    cp16(s0 + OFF_AL + so1, Agl + (size_t)u_row1 * Dd + koff + u_u1 * 8);           \
    cp16(s0 + OFF_BH + so0, Bgh + (size_t)u_row0 * Dd + koff + u_u0 * 8);           \
    cp16(s0 + OFF_BH + so1, Bgh + (size_t)u_row1 * Dd + koff + u_u1 * 8);           \
    cp16(s0 + OFF_BL + so0, Bgl + (size_t)u_row0 * Dd + koff + u_u0 * 8);           \
    cp16(s0 + OFF_BL + so1, Bgl + (size_t)u_row1 * Dd + koff + u_u1 * 8);           \
} while (0)

    float acc[4][4][4];
#pragma unroll
    for (int i = 0; i < 4; i++)
#pragma unroll
        for (int j = 0; j < 4; j++)
#pragma unroll
            for (int q = 0; q < 4; q++) acc[i][j][q] = 0.f;

    LOAD_STAGE(0, 0);
    asm volatile("cp.async.commit_group;" ::: "memory");
    LOAD_STAGE(1, 1);
    asm volatile("cp.async.commit_group;" ::: "memory");

    const int arow_base = warp_m * 64 + (lane & 15);
    const int nrow_base = warp_n * 32 + ((lane >> 4) << 3) + (lane & 7);

    const int NIT = Dd / 32;   // 8
    for (int it = 0; it < NIT; it++) {
        asm volatile("cp.async.wait_group 1;" ::: "memory");
        __syncthreads();
        if (it + 2 < NIT) {
            int st = (it + 2) % 3;
            LOAD_STAGE(st, it + 2);
        }
        asm volatile("cp.async.commit_group;" ::: "memory");

        const uint32_t stg = sbase + (it % 3) * STAGE_BYTES;
#pragma unroll
        for (int ks = 0; ks < 2; ks++) {
            const int akk = ks * 16 + (lane >> 4) * 8;
            const int bkk = ks * 16 + ((lane >> 3) & 1) * 8;

            uint32_t bh[2][4], blo[2][4];
#pragma unroll
            for (int ib = 0; ib < 2; ib++) {
                int row = nrow_base + ib * 16;
                uint32_t off = row * 64 + ((((bkk >> 3)) ^ ((row >> 1) & 3)) << 4);
                ldmx4(bh[ib], stg + OFF_BH + off);
                ldmx4(blo[ib], stg + OFF_BL + off);
            }
#pragma unroll
            for (int im = 0; im < 4; im++) {
                int row = arow_base + im * 16;
                uint32_t aoff = row * 64 + ((((akk >> 3)) ^ ((row >> 1) & 3)) << 4);
                uint32_t ah[4], al[4];
                ldmx4(ah, stg + OFF_AH + aoff);
                ldmx4(al, stg + OFF_AL + aoff);   // hoisted: latency hidden behind ah MMAs
#pragma unroll
                for (int in = 0; in < 4; in++)
                    mma16816(acc[im][in], ah,
                             bh[in >> 1][(in & 1) * 2], bh[in >> 1][(in & 1) * 2 + 1]);
#pragma unroll
                for (int in = 0; in < 4; in++)
                    mma16816(acc[im][in], ah,
                             blo[in >> 1][(in & 1) * 2], blo[in >> 1][(in & 1) * 2 + 1]);
#pragma unroll
                for (int in = 0; in < 4; in++)
                    mma16816(acc[im][in], al,
                             bh[in >> 1][(in & 1) * 2], bh[in >> 1][(in & 1) * 2 + 1]);
            }
        }
    }

    // epilogue: Y = acc + bias
    float* Yb = g_y + (size_t)bl * Ss * DOo;
    const float* bp = bias + l * DOo;
#pragma unroll
    for (int im = 0; im < 4; im++) {
        int m = m0 + warp_m * 64 + im * 16 + (lane >> 2);
#pragma unroll
        for (int in = 0; in < 4; in++) {
            int n = n0 + warp_n * 32 + in * 8 + 2 * (lane & 3);
            float bx = bp[n], by = bp[n + 1];
            float2 o0 = { acc[im][in][0] + bx, acc[im][in][1] + by };
            float2 o1 = { acc[im][in][2] + bx, acc[im][in][3] + by };
            *reinterpret_cast<float2*>(Yb + (size_t)m * DOo + n) = o0;
            *reinterpret_cast<float2*>(Yb + (size_t)(m + 8) * DOo + n) = o1;
        }
    }
#undef LOAD_STAGE
}

// ================= gather-reduce + ReLU (per-batch, 128 threads, float2) =========
__global__ __launch_bounds__(128) void k_gather(float* __restrict__ out, int bconst) {
    const int r = bconst * Ss + blockIdx.x;
    const int o = threadIdx.x * 2;     // 0..254
    const int beg = g_offs[r];
    const int end = g_offs[r + 1];
    const float* Yb = g_y + (size_t)bconst * Ll * Ss * DOo;

    float2 a0 = {0.f, 0.f}, a1 = {0.f, 0.f}, a2 = {0.f, 0.f}, a3 = {0.f, 0.f};
    int i = beg;
    for (; i + 3 < end; i += 4) {
        int p0 = __ldg(&g_perm[i]);
        int p1 = __ldg(&g_perm[i + 1]);
        int p2 = __ldg(&g_perm[i + 2]);
        int p3 = __ldg(&g_perm[i + 3]);
        float2 v0 = *reinterpret_cast<const float2*>(Yb + (size_t)p0 * DOo + o);
        float2 v1 = *reinterpret_cast<const float2*>(Yb + (size_t)p1 * DOo + o);
        float2 v2 = *reinterpret_cast<const float2*>(Yb + (size_t)p2 * DOo + o);
        float2 v3 = *reinterpret_cast<const float2*>(Yb + (size_t)p3 * DOo + o);
        a0.x += v0.x; a0.y += v0.y;
        a1.x += v1.x; a1.y += v1.y;
        a2.x += v2.x; a2.y += v2.y;
        a3.x += v3.x; a3.y += v3.y;
    }
    for (; i < end; i++) {
        float2 v = *reinterpret_cast<const float2*>(
            Yb + (size_t)__ldg(&g_perm[i]) * DOo + o);
        a0.x += v.x; a0.y += v.y;
    }
    float2 res;
    res.x = fmaxf((a0.x + a1.x) + (a2.x + a3.x), 0.f);
    res.y = fmaxf((a0.y + a1.y) + (a2.y + a3.y), 0.f);
    *reinterpret_cast<float2*>(out + (size_t)r * DOo + o) = res;
}

// ================= launch =================
extern "C" void kernel_launch(void* const* d_in, const int* in_sizes, int n_in,
                              void* d_out, int out_size) {
    const float* X    = (const float*)d_in[0];
    const int*   esrc = (const int*)d_in[1];
    const int*   etgt = (const int*)d_in[2];
    const int*   elab = (const int*)d_in[3];
    const float* W    = (const float*)d_in[4];
    const float* bias = (const float*)d_in[5];
    float* out = (float*)d_out;

    const int SMEM_BYTES = 3 * STAGE_BYTES;   // 96 KB
    cudaFuncSetAttribute(k_gemm_mma, cudaFuncAttributeMaxDynamicSharedMemorySize, SMEM_BYTES);
    dim3 ggrid(Ss / 128, DOo / 128, Ll);      // 256 CTAs per batch

    if (g_streams_ok) {
        // fork side stream
        cudaEventRecord(g_ev0, 0);
        cudaStreamWaitEvent(g_s2, g_ev0, 0);

        // CSR build on side stream (independent of prep/GEMM)
        k_zero_deg<<<(Bb * Ss + 255) / 256, 256, 0, g_s2>>>();
        k_hist<<<(Bb * Ee + 255) / 256, 256, 0, g_s2>>>(etgt);
        k_scan<<<1, 1024, 0, g_s2>>>();
        k_fill<<<(Bb * Ee + 255) / 256, 256, 0, g_s2>>>(etgt, elab, esrc);

        // main stream: prep then per-batch GEMMs, each followed by an event
        k_prep<<<(Bb * Ss * Dd + 255) / 256, 256>>>(X, W);
        for (int b = 0; b < Bb; b++) {
            k_gemm_mma<<<ggrid, 256, SMEM_BYTES>>>(bias, b);
            cudaEventRecord(g_evG[b], 0);
        }

        // side stream: per-batch gathers, each after its batch's GEMM
        for (int b = 0; b < Bb; b++) {
            cudaStreamWaitEvent(g_s2, g_evG[b], 0);
            k_gather<<<Ss, 128, 0, g_s2>>>(out, b);
        }
        cudaEventRecord(g_ev1, g_s2);
        cudaStreamWaitEvent(0, g_ev1, 0);     // join
    } else {
        // sequential fallback
        k_zero_deg<<<(Bb * Ss + 255) / 256, 256>>>();
        k_hist<<<(Bb * Ee + 255) / 256, 256>>>(etgt);
        k_scan<<<1, 1024>>>();
        k_fill<<<(Bb * Ee + 255) / 256, 256>>>(etgt, elab, esrc);
        k_prep<<<(Bb * Ss * Dd + 255) / 256, 256>>>(X, W);
        for (int b = 0; b < Bb; b++) k_gemm_mma<<<ggrid, 256, SMEM_BYTES>>>(bias, b);
        for (int b = 0; b < Bb; b++) k_gather<<<Ss, 128>>>(out, b);
    }
}

// round 8
// speedup vs baseline: 1.0826x; 1.0826x over previous
#include <cuda_runtime.h>
#include <cuda_bf16.h>
#include <cstdint>

#define Bb  8
#define Ss  2048
#define Dd  256
#define DOo 256
#define Ll  8
#define Ee  32768

// ---- static device scratch ----
__device__ float g_y[(size_t)Bb * Ll * Ss * DOo];                     // 128 MiB
__device__ __align__(128) __nv_bfloat16 g_xh[(size_t)Bb * Ss * Dd];   // 8 MiB
__device__ __align__(128) __nv_bfloat16 g_xl[(size_t)Bb * Ss * Dd];   // 8 MiB
__device__ __align__(128) __nv_bfloat16 g_wh[(size_t)Ll * DOo * Dd];  // 1 MiB [l][n][k]
__device__ __align__(128) __nv_bfloat16 g_wl[(size_t)Ll * DOo * Dd];  // 1 MiB
__device__ int g_deg[Bb * Ss];
__device__ int g_offs[Bb * Ss + 1];
__device__ int g_cursor[Bb * Ss];
__device__ int g_perm[Bb * Ee];                                       // l*Ss + s

// ---- streams + events, created once at process init (outside capture) ----
static cudaStream_t g_s2 = nullptr;
static cudaEvent_t g_ev0 = nullptr, g_ev1 = nullptr;
static cudaEvent_t g_evH0 = nullptr, g_evH1 = nullptr, g_evCSR = nullptr;
static bool g_streams_ok = false;
namespace {
struct _StreamInit {
    _StreamInit() {
        bool ok = true;
        ok &= (cudaStreamCreateWithFlags(&g_s2, cudaStreamNonBlocking) == cudaSuccess);
        ok &= (cudaEventCreateWithFlags(&g_ev0, cudaEventDisableTiming) == cudaSuccess);
        ok &= (cudaEventCreateWithFlags(&g_ev1, cudaEventDisableTiming) == cudaSuccess);
        ok &= (cudaEventCreateWithFlags(&g_evH0, cudaEventDisableTiming) == cudaSuccess);
        ok &= (cudaEventCreateWithFlags(&g_evH1, cudaEventDisableTiming) == cudaSuccess);
        ok &= (cudaEventCreateWithFlags(&g_evCSR, cudaEventDisableTiming) == cudaSuccess);
        g_streams_ok = ok;
    }
} _stream_init;
}

// ================= CSR-build kernels =================
__global__ void k_zero_deg() {
    int i = blockIdx.x * blockDim.x + threadIdx.x;
    if (i < Bb * Ss) g_deg[i] = 0;
}
__global__ void k_hist(const int* __restrict__ tgt) {
    int i = blockIdx.x * blockDim.x + threadIdx.x;
    if (i < Bb * Ee) {
        int b = i / Ee;
        atomicAdd(&g_deg[b * Ss + tgt[i]], 1);
    }
}
__global__ void k_scan() {   // 1024 threads, 16 rows each
    const int t = threadIdx.x;
    const int base = t * 16;
    int loc[16]; int sum = 0;
#pragma unroll
    for (int i = 0; i < 16; i++) { loc[i] = sum; sum += g_deg[base + i]; }
    int lane = t & 31, warp = t >> 5;
    int v = sum;
#pragma unroll
    for (int o = 1; o < 32; o <<= 1) {
        int u = __shfl_up_sync(0xFFFFFFFF, v, o);
        if (lane >= o) v += u;
    }
    __shared__ int wsum[32];
    if (lane == 31) wsum[warp] = v;
    __syncthreads();
    if (warp == 0) {
        int w = wsum[lane];
#pragma unroll
        for (int o = 1; o < 32; o <<= 1) {
            int u = __shfl_up_sync(0xFFFFFFFF, w, o);
            if (lane >= o) w += u;
        }
        wsum[lane] = w;
    }
    __syncthreads();
    int pre = v - sum + (warp ? wsum[warp - 1] : 0);
#pragma unroll
    for (int i = 0; i < 16; i++) {
        int o = pre + loc[i];
        g_offs[base + i]   = o;
        g_cursor[base + i] = o;
    }
    if (t == 1023) g_offs[Bb * Ss] = wsum[31];
}
__global__ void k_fill(const int* __restrict__ tgt, const int* __restrict__ lab,
                       const int* __restrict__ src) {
    int i = blockIdx.x * blockDim.x + threadIdx.x;
    if (i < Bb * Ee) {
        int b = i / Ee;
        int pos = atomicAdd(&g_cursor[b * Ss + tgt[i]], 1);
        g_perm[pos] = lab[i] * Ss + src[i];
    }
}

// ================= prep: split X + split W into bf16 hi/lo =================
__global__ void k_prep(const float* __restrict__ X, const float* __restrict__ W) {
    int i = blockIdx.x * blockDim.x + threadIdx.x;
    if (i < Bb * Ss * Dd) {
        float v = X[i];
        __nv_bfloat16 h = __float2bfloat16(v);
        g_xh[i] = h;
        g_xl[i] = __float2bfloat16(v - __bfloat162float(h));
    }
    if (i < Ll * Dd * DOo) {
        int l = i / (Dd * DOo);
        int r = i - l * (Dd * DOo);
        int k = r >> 8;
        int n = r & 255;
        float v = W[i];
        __nv_bfloat16 h = __float2bfloat16(v);
        size_t o = ((size_t)l * DOo + n) * Dd + k;
        g_wh[o] = h;
        g_wl[o] = __float2bfloat16(v - __bfloat162float(h));
    }
}

// ================= bf16x3 mma.sync GEMM (half-batch group) =================
__device__ __forceinline__ uint32_t s2u(const void* p) {
    uint32_t a;
    asm("{ .reg .u64 t; cvta.to.shared.u64 t, %1; cvt.u32.u64 %0, t; }" : "=r"(a) : "l"(p));
    return a;
}
__device__ __forceinline__ void cp16(uint32_t sa, const void* ga) {
    asm volatile("cp.async.cg.shared.global [%0], [%1], 16;" :: "r"(sa), "l"(ga));
}
__device__ __forceinline__ void ldmx4(uint32_t* r, uint32_t addr) {
    asm volatile("ldmatrix.sync.aligned.m8n8.x4.shared.b16 {%0,%1,%2,%3}, [%4];"
                 : "=r"(r[0]), "=r"(r[1]), "=r"(r[2]), "=r"(r[3]) : "r"(addr));
}
__device__ __forceinline__ void mma16816(float* c, const uint32_t* a,
                                         uint32_t b0, uint32_t b1) {
    asm volatile(
        "mma.sync.aligned.m16n8k16.row.col.f32.bf16.bf16.f32 "
        "{%0,%1,%2,%3}, {%4,%5,%6,%7}, {%8,%9}, {%0,%1,%2,%3};"
        : "+f"(c[0]), "+f"(c[1]), "+f"(c[2]), "+f"(c[3])
        : "r"(a[0]), "r"(a[1]), "r"(a[2]), "r"(a[3]), "r"(b0), "r"(b1));
}

#define STAGE_BYTES 32768      // 4 tiles x 8KB (Ah, Al, Bh, Bl), 128 rows x 64B each
#define OFF_AH 0
#define OFF_AL 8192
#define OFF_BH 16384
#define OFF_BL 24576

// grid: (Ss/128, DOo/128, 4*Ll); batch = b_base + z>>3, label = z&7
__global__ __launch_bounds__(256, 2) void k_gemm_mma(const float* __restrict__ bias,
                                                     int b_base) {
    extern __shared__ char smem[];
    const uint32_t sbase = s2u(smem);          // 3 stages x 32KB

    const int tid = threadIdx.x;
    const int lane = tid & 31;
    const int wid = tid >> 5;
    const int warp_m = wid & 1;                // 2 x 64 rows
    const int warp_n = wid >> 1;               // 4 x 32 cols
    const int z = blockIdx.z;
    const int b = b_base + (z >> 3);
    const int l = z & 7;
    const int bl = b * Ll + l;
    const int m0 = blockIdx.x * 128;
    const int n0 = blockIdx.y * 128;

    const __nv_bfloat16* Agh = g_xh + ((size_t)(b * Ss) + m0) * Dd;
    const __nv_bfloat16* Agl = g_xl + ((size_t)(b * Ss) + m0) * Dd;
    const __nv_bfloat16* Bgh = g_wh + ((size_t)l * DOo + n0) * Dd;
    const __nv_bfloat16* Bgl = g_wl + ((size_t)l * DOo + n0) * Dd;

    const int u_row0 = tid >> 2,          u_u0 = tid & 3;
    const int u_row1 = (tid + 256) >> 2,  u_u1 = (tid + 256) & 3;
    const uint32_t so0 = (uint32_t)(u_row0 * 64 + ((u_u0 ^ ((u_row0 >> 1) & 3)) << 4));
    const uint32_t so1 = (uint32_t)(u_row1 * 64 + ((u_u1 ^ ((u_row1 >> 1) & 3)) << 4));

#define LOAD_STAGE(st, it) do {                                                     \
    int koff = (it) * 32;                                                           \
    uint32_t s0 = sbase + (st) * STAGE_BYTES;                                       \
    cp16(s0 + OFF_AH + so0, Agh + (size_t)u_row0 * Dd + koff + u_u0 * 8);           \
    cp16(s0 + OFF_AH + so1, Agh + (size_t)u_row1 * Dd + koff + u_u1 * 8);           \
    cp16(s0 + OFF_AL + so0, Agl + (size_t)u_row0 * Dd + koff + u_u0 * 8);           \
    cp16(s0 + OFF_AL + so1, Agl + (size_t)u_row1 * Dd + koff + u_u1 * 8);           \
    cp16(s0 + OFF_BH + so0, Bgh + (size_t)u_row0 * Dd + koff + u_u0 * 8);           \
    cp16(s0 + OFF_BH + so1, Bgh + (size_t)u_row1 * Dd + koff + u_u1 * 8);           \
    cp16(s0 + OFF_BL + so0, Bgl + (size_t)u_row0 * Dd + koff + u_u0 * 8);           \
    cp16(s0 + OFF_BL + so1, Bgl + (size_t)u_row1 * Dd + koff + u_u1 * 8);           \
} while (0)

    float acc[4][4][4];
#pragma unroll
    for (int i = 0; i < 4; i++)
#pragma unroll
        for (int j = 0; j < 4; j++)
#pragma unroll
            for (int q = 0; q < 4; q++) acc[i][j][q] = 0.f;

    LOAD_STAGE(0, 0);
    asm volatile("cp.async.commit_group;" ::: "memory");
    LOAD_STAGE(1, 1);
    asm volatile("cp.async.commit_group;" ::: "memory");

    const int arow_base = warp_m * 64 + (lane & 15);
    const int nrow_base = warp_n * 32 + ((lane >> 4) << 3) + (lane & 7);

    const int NIT = Dd / 32;   // 8
    for (int it = 0; it < NIT; it++) {
        asm volatile("cp.async.wait_group 1;" ::: "memory");
        __syncthreads();
        if (it + 2 < NIT) {
            int st = (it + 2) % 3;
            LOAD_STAGE(st, it + 2);
        }
        asm volatile("cp.async.commit_group;" ::: "memory");

        const uint32_t stg = sbase + (it % 3) * STAGE_BYTES;
#pragma unroll
        for (int ks = 0; ks < 2; ks++) {
            const int akk = ks * 16 + (lane >> 4) * 8;
            const int bkk = ks * 16 + ((lane >> 3) & 1) * 8;

            uint32_t bh[2][4], blo[2][4];
#pragma unroll
            for (int ib = 0; ib < 2; ib++) {
                int row = nrow_base + ib * 16;
                uint32_t off = row * 64 + ((((bkk >> 3)) ^ ((row >> 1) & 3)) << 4);
                ldmx4(bh[ib], stg + OFF_BH + off);
                ldmx4(blo[ib], stg + OFF_BL + off);
            }
#pragma unroll
            for (int im = 0; im < 4; im++) {
                int row = arow_base + im * 16;
                uint32_t aoff = row * 64 + ((((akk >> 3)) ^ ((row >> 1) & 3)) << 4);
                uint32_t ah[4], al[4];
                ldmx4(ah, stg + OFF_AH + aoff);
                ldmx4(al, stg + OFF_AL + aoff);
#pragma unroll
                for (int in = 0; in < 4; in++)
                    mma16816(acc[im][in], ah,
                             bh[in >> 1][(in & 1) * 2], bh[in >> 1][(in & 1) * 2 + 1]);
#pragma unroll
                for (int in = 0; in < 4; in++)
                    mma16816(acc[im][in], ah,
                             blo[in >> 1][(in & 1) * 2], blo[in >> 1][(in & 1) * 2 + 1]);
#pragma unroll
                for (int in = 0; in < 4; in++)
                    mma16816(acc[im][in], al,
                             bh[in >> 1][(in & 1) * 2], bh[in >> 1][(in & 1) * 2 + 1]);
            }
        }
    }

    // epilogue: Y = acc + bias
    float* Yb = g_y + (size_t)bl * Ss * DOo;
    const float* bp = bias + l * DOo;
#pragma unroll
    for (int im = 0; im < 4; im++) {
        int m = m0 + warp_m * 64 + im * 16 + (lane >> 2);
#pragma unroll
        for (int in = 0; in < 4; in++) {
            int n = n0 + warp_n * 32 + in * 8 + 2 * (lane & 3);
            float bx = bp[n], by = bp[n + 1];
            float2 o0 = { acc[im][in][0] + bx, acc[im][in][1] + by };
            float2 o1 = { acc[im][in][2] + bx, acc[im][in][3] + by };
            *reinterpret_cast<float2*>(Yb + (size_t)m * DOo + n) = o0;
            *reinterpret_cast<float2*>(Yb + (size_t)(m + 8) * DOo + n) = o1;
        }
    }
#undef LOAD_STAGE
}

// ================= gather-reduce + ReLU (half-batch group) =================
// grid: 4*Ss blocks; row r = b_base*Ss + blockIdx.x
__global__ __launch_bounds__(128) void k_gather(float* __restrict__ out, int b_base) {
    const int r = b_base * Ss + blockIdx.x;
    const int b = r >> 11;
    const int o = threadIdx.x * 2;     // 0..254
    const int beg = g_offs[r];
    const int end = g_offs[r + 1];
    const float* Yb = g_y + (size_t)b * Ll * Ss * DOo;

    float2 a0 = {0.f, 0.f}, a1 = {0.f, 0.f}, a2 = {0.f, 0.f}, a3 = {0.f, 0.f};
    int i = beg;
    for (; i + 3 < end; i += 4) {
        int p0 = __ldg(&g_perm[i]);
        int p1 = __ldg(&g_perm[i + 1]);
        int p2 = __ldg(&g_perm[i + 2]);
        int p3 = __ldg(&g_perm[i + 3]);
        float2 v0 = *reinterpret_cast<const float2*>(Yb + (size_t)p0 * DOo + o);
        float2 v1 = *reinterpret_cast<const float2*>(Yb + (size_t)p1 * DOo + o);
        float2 v2 = *reinterpret_cast<const float2*>(Yb + (size_t)p2 * DOo + o);
        float2 v3 = *reinterpret_cast<const float2*>(Yb + (size_t)p3 * DOo + o);
        a0.x += v0.x; a0.y += v0.y;
        a1.x += v1.x; a1.y += v1.y;
        a2.x += v2.x; a2.y += v2.y;
        a3.x += v3.x; a3.y += v3.y;
    }
    for (; i < end; i++) {
        float2 v = *reinterpret_cast<const float2*>(
            Yb + (size_t)__ldg(&g_perm[i]) * DOo + o);
        a0.x += v.x; a0.y += v.y;
    }
    float2 res;
    res.x = fmaxf((a0.x + a1.x) + (a2.x + a3.x), 0.f);
    res.y = fmaxf((a0.y + a1.y) + (a2.y + a3.y), 0.f);
    *reinterpret_cast<float2*>(out + (size_t)r * DOo + o) = res;
}

// ================= launch =================
extern "C" void kernel_launch(void* const* d_in, const int* in_sizes, int n_in,
                              void* d_out, int out_size) {
    const float* X    = (const float*)d_in[0];
    const int*   esrc = (const int*)d_in[1];
    const int*   etgt = (const int*)d_in[2];
    const int*   elab = (const int*)d_in[3];
    const float* W    = (const float*)d_in[4];
    const float* bias = (const float*)d_in[5];
    float* out = (float*)d_out;

    const int SMEM_BYTES = 3 * STAGE_BYTES;   // 96 KB
    cudaFuncSetAttribute(k_gemm_mma, cudaFuncAttributeMaxDynamicSharedMemorySize, SMEM_BYTES);
    dim3 ggrid(Ss / 128, DOo / 128, 4 * Ll);  // 1024 CTAs per half

    if (g_streams_ok) {
        // fork side stream
        cudaEventRecord(g_ev0, 0);
        cudaStreamWaitEvent(g_s2, g_ev0, 0);

        // CSR build on side stream (independent of prep/GEMM)
        k_zero_deg<<<(Bb * Ss + 255) / 256, 256, 0, g_s2>>>();
        k_hist<<<(Bb * Ee + 255) / 256, 256, 0, g_s2>>>(etgt);
        k_scan<<<1, 1024, 0, g_s2>>>();
        k_fill<<<(Bb * Ee + 255) / 256, 256, 0, g_s2>>>(etgt, elab, esrc);
        cudaEventRecord(g_evCSR, g_s2);

        // main stream: prep, then GEMM halves
        k_prep<<<(Bb * Ss * Dd + 255) / 256, 256>>>(X, W);
        k_gemm_mma<<<ggrid, 256, SMEM_BYTES>>>(bias, 0);     // batches 0-3
        cudaEventRecord(g_evH0, 0);
        k_gemm_mma<<<ggrid, 256, SMEM_BYTES>>>(bias, 4);     // batches 4-7
        cudaEventRecord(g_evH1, 0);

        // side stream: gather first half overlapping second GEMM half
        cudaStreamWaitEvent(g_s2, g_evH0, 0);
        k_gather<<<4 * Ss, 128, 0, g_s2>>>(out, 0);
        cudaStreamWaitEvent(g_s2, g_evH1, 0);
        k_gather<<<4 * Ss, 128, 0, g_s2>>>(out, 4);
        cudaEventRecord(g_ev1, g_s2);
        cudaStreamWaitEvent(0, g_ev1, 0);     // join
    } else {
        // sequential fallback
        k_zero_deg<<<(Bb * Ss + 255) / 256, 256>>>();
        k_hist<<<(Bb * Ee + 255) / 256, 256>>>(etgt);
        k_scan<<<1, 1024>>>();
        k_fill<<<(Bb * Ee + 255) / 256, 256>>>(etgt, elab, esrc);
        k_prep<<<(Bb * Ss * Dd + 255) / 256, 256>>>(X, W);
        k_gemm_mma<<<ggrid, 256, SMEM_BYTES>>>(bias, 0);
        k_gemm_mma<<<ggrid, 256, SMEM_BYTES>>>(bias, 4);
        k_gather<<<4 * Ss, 128>>>(out, 0);
        k_gather<<<4 * Ss, 128>>>(out, 4);
    }
}

// round 9
// speedup vs baseline: 1.7581x; 1.6240x over previous
#include <cuda_runtime.h>
#include <cuda_fp16.h>
#include <cstdint>

#define Bb  8
#define Ss  2048
#define Dd  256
#define DOo 256
#define Ll  8
#define Ee  32768

// ---- static device scratch ----
__device__ float g_y[(size_t)Bb * Ll * Ss * DOo];                  // 128 MiB
__device__ __align__(128) __half g_xf[(size_t)Bb * Ss * Dd];       // 8 MiB
__device__ __align__(128) __half g_wf[(size_t)Ll * DOo * Dd];      // 1 MiB [l][n][k]
__device__ int g_deg[Bb * Ss];
__device__ int g_offs[Bb * Ss + 1];
__device__ int g_cursor[Bb * Ss];
__device__ int g_perm[Bb * Ee];                                    // l*Ss + s

// ---- streams + events, created once at process init (outside capture) ----
static cudaStream_t g_s2 = nullptr;
static cudaEvent_t g_ev0 = nullptr, g_ev1 = nullptr;
static cudaEvent_t g_evH0 = nullptr, g_evH1 = nullptr;
static bool g_streams_ok = false;
namespace {
struct _StreamInit {
    _StreamInit() {
        bool ok = true;
        ok &= (cudaStreamCreateWithFlags(&g_s2, cudaStreamNonBlocking) == cudaSuccess);
        ok &= (cudaEventCreateWithFlags(&g_ev0, cudaEventDisableTiming) == cudaSuccess);
        ok &= (cudaEventCreateWithFlags(&g_ev1, cudaEventDisableTiming) == cudaSuccess);
        ok &= (cudaEventCreateWithFlags(&g_evH0, cudaEventDisableTiming) == cudaSuccess);
        ok &= (cudaEventCreateWithFlags(&g_evH1, cudaEventDisableTiming) == cudaSuccess);
        g_streams_ok = ok;
    }
} _stream_init;
}

// ================= CSR-build kernels =================
__global__ void k_zero_deg() {
    int i = blockIdx.x * blockDim.x + threadIdx.x;
    if (i < Bb * Ss) g_deg[i] = 0;
}
__global__ void k_hist(const int* __restrict__ tgt) {
    int i = blockIdx.x * blockDim.x + threadIdx.x;
    if (i < Bb * Ee) {
        int b = i / Ee;
        atomicAdd(&g_deg[b * Ss + tgt[i]], 1);
    }
}
__global__ void k_scan() {   // 1024 threads, 16 rows each
    const int t = threadIdx.x;
    const int base = t * 16;
    int loc[16]; int sum = 0;
#pragma unroll
    for (int i = 0; i < 16; i++) { loc[i] = sum; sum += g_deg[base + i]; }
    int lane = t & 31, warp = t >> 5;
    int v = sum;
#pragma unroll
    for (int o = 1; o < 32; o <<= 1) {
        int u = __shfl_up_sync(0xFFFFFFFF, v, o);
        if (lane >= o) v += u;
    }
    __shared__ int wsum[32];
    if (lane == 31) wsum[warp] = v;
    __syncthreads();
    if (warp == 0) {
        int w = wsum[lane];
#pragma unroll
        for (int o = 1; o < 32; o <<= 1) {
            int u = __shfl_up_sync(0xFFFFFFFF, w, o);
            if (lane >= o) w += u;
        }
        wsum[lane] = w;
    }
    __syncthreads();
    int pre = v - sum + (warp ? wsum[warp - 1] : 0);
#pragma unroll
    for (int i = 0; i < 16; i++) {
        int o = pre + loc[i];
        g_offs[base + i]   = o;
        g_cursor[base + i] = o;
    }
    if (t == 1023) g_offs[Bb * Ss] = wsum[31];
}
__global__ void k_fill(const int* __restrict__ tgt, const int* __restrict__ lab,
                       const int* __restrict__ src) {
    int i = blockIdx.x * blockDim.x + threadIdx.x;
    if (i < Bb * Ee) {
        int b = i / Ee;
        int pos = atomicAdd(&g_cursor[b * Ss + tgt[i]], 1);
        g_perm[pos] = lab[i] * Ss + src[i];
    }
}

// ================= prep: fp32 -> fp16 casts =================
__global__ void k_prep(const float* __restrict__ X, const float* __restrict__ W) {
    int i = blockIdx.x * blockDim.x + threadIdx.x;
    if (i < Bb * Ss * Dd) g_xf[i] = __float2half(X[i]);
    if (i < Ll * Dd * DOo) {
        int l = i / (Dd * DOo);
        int r = i - l * (Dd * DOo);
        int k = r >> 8;
        int n = r & 255;
        g_wf[((size_t)l * DOo + n) * Dd + k] = __float2half(W[i]);
    }
}

// ================= fp16 mma.sync GEMM (half-batch group) =================
__device__ __forceinline__ uint32_t s2u(const void* p) {
    uint32_t a;
    asm("{ .reg .u64 t; cvta.to.shared.u64 t, %1; cvt.u32.u64 %0, t; }" : "=r"(a) : "l"(p));
    return a;
}
__device__ __forceinline__ void cp16(uint32_t sa, const void* ga) {
    asm volatile("cp.async.cg.shared.global [%0], [%1], 16;" :: "r"(sa), "l"(ga));
}
__device__ __forceinline__ void ldmx4(uint32_t* r, uint32_t addr) {
    asm volatile("ldmatrix.sync.aligned.m8n8.x4.shared.b16 {%0,%1,%2,%3}, [%4];"
                 : "=r"(r[0]), "=r"(r[1]), "=r"(r[2]), "=r"(r[3]) : "r"(addr));
}
__device__ __forceinline__ void mma16816(float* c, const uint32_t* a,
                                         uint32_t b0, uint32_t b1) {
    asm volatile(
        "mma.sync.aligned.m16n8k16.row.col.f32.f16.f16.f32 "
        "{%0,%1,%2,%3}, {%4,%5,%6,%7}, {%8,%9}, {%0,%1,%2,%3};"
        : "+f"(c[0]), "+f"(c[1]), "+f"(c[2]), "+f"(c[3])
        : "r"(a[0]), "r"(a[1]), "r"(a[2]), "r"(a[3]), "r"(b0), "r"(b1));
}

#define STAGE_BYTES 16384      // 2 tiles x 8KB (A, B), 128 rows x 64B each
#define OFF_A 0
#define OFF_B 8192
#define NSTAGE 4

// grid: (Ss/128, DOo/128, 4*Ll); batch = b_base + z>>3, label = z&7
__global__ __launch_bounds__(256, 2) void k_gemm_mma(const float* __restrict__ bias,
                                                     int b_base) {
    extern __shared__ char smem[];
    const uint32_t sbase = s2u(smem);          // 4 stages x 16KB

    const int tid = threadIdx.x;
    const int lane = tid & 31;
    const int wid = tid >> 5;
    const int warp_m = wid & 1;                // 2 x 64 rows
    const int warp_n = wid >> 1;               // 4 x 32 cols
    const int z = blockIdx.z;
    const int b = b_base + (z >> 3);
    const int l = z & 7;
    const int bl = b * Ll + l;
    const int m0 = blockIdx.x * 128;
    const int n0 = blockIdx.y * 128;

    const __half* Ag = g_xf + ((size_t)(b * Ss) + m0) * Dd;
    const __half* Bg = g_wf + ((size_t)l * DOo + n0) * Dd;

    // 512 16B-units per tile, 256 threads -> 2 units/thread/tile
    const int u_row0 = tid >> 2,          u_u0 = tid & 3;
    const int u_row1 = (tid + 256) >> 2,  u_u1 = (tid + 256) & 3;
    const uint32_t so0 = (uint32_t)(u_row0 * 64 + ((u_u0 ^ ((u_row0 >> 1) & 3)) << 4));
    const uint32_t so1 = (uint32_t)(u_row1 * 64 + ((u_u1 ^ ((u_row1 >> 1) & 3)) << 4));

#define LOAD_STAGE(st, it) do {                                                     \
    int koff = (it) * 32;                                                           \
    uint32_t s0 = sbase + (st) * STAGE_BYTES;                                       \
    cp16(s0 + OFF_A + so0, Ag + (size_t)u_row0 * Dd + koff + u_u0 * 8);             \
    cp16(s0 + OFF_A + so1, Ag + (size_t)u_row1 * Dd + koff + u_u1 * 8);             \
    cp16(s0 + OFF_B + so0, Bg + (size_t)u_row0 * Dd + koff + u_u0 * 8);             \
    cp16(s0 + OFF_B + so1, Bg + (size_t)u_row1 * Dd + koff + u_u1 * 8);             \
} while (0)

    float acc[4][4][4];
#pragma unroll
    for (int i = 0; i < 4; i++)
#pragma unroll
        for (int j = 0; j < 4; j++)
#pragma unroll
            for (int q = 0; q < 4; q++) acc[i][j][q] = 0.f;

    LOAD_STAGE(0, 0);
    asm volatile("cp.async.commit_group;" ::: "memory");
    LOAD_STAGE(1, 1);
    asm volatile("cp.async.commit_group;" ::: "memory");
    LOAD_STAGE(2, 2);
    asm volatile("cp.async.commit_group;" ::: "memory");

    const int arow_base = warp_m * 64 + (lane & 15);
    const int nrow_base = warp_n * 32 + ((lane >> 4) << 3) + (lane & 7);

    const int NIT = Dd / 32;   // 8
    for (int it = 0; it < NIT; it++) {
        asm volatile("cp.async.wait_group 2;" ::: "memory");
        __syncthreads();
        if (it + 3 < NIT) {
            int st = (it + 3) % NSTAGE;
            LOAD_STAGE(st, it + 3);
        }
        asm volatile("cp.async.commit_group;" ::: "memory");

        const uint32_t stg = sbase + (it % NSTAGE) * STAGE_BYTES;
#pragma unroll
        for (int ks = 0; ks < 2; ks++) {
            const int akk = ks * 16 + (lane >> 4) * 8;
            const int bkk = ks * 16 + ((lane >> 3) & 1) * 8;

            uint32_t af[4][4], bf[2][4];
#pragma unroll
            for (int im = 0; im < 4; im++) {
                int row = arow_base + im * 16;
                uint32_t off = row * 64 + ((((akk >> 3)) ^ ((row >> 1) & 3)) << 4);
                ldmx4(af[im], stg + OFF_A + off);
            }
#pragma unroll
            for (int ib = 0; ib < 2; ib++) {
                int row = nrow_base + ib * 16;
                uint32_t off = row * 64 + ((((bkk >> 3)) ^ ((row >> 1) & 3)) << 4);
                ldmx4(bf[ib], stg + OFF_B + off);
            }
#pragma unroll
            for (int im = 0; im < 4; im++)
#pragma unroll
                for (int in = 0; in < 4; in++)
                    mma16816(acc[im][in], af[im],
                             bf[in >> 1][(in & 1) * 2], bf[in >> 1][(in & 1) * 2 + 1]);
        }
    }

    // epilogue: Y = acc + bias
    float* Yb = g_y + (size_t)bl * Ss * DOo;
    const float* bp = bias + l * DOo;
#pragma unroll
    for (int im = 0; im < 4; im++) {
        int m = m0 + warp_m * 64 + im * 16 + (lane >> 2);
#pragma unroll
        for (int in = 0; in < 4; in++) {
            int n = n0 + warp_n * 32 + in * 8 + 2 * (lane & 3);
            float bx = bp[n], by = bp[n + 1];
            float2 o0 = { acc[im][in][0] + bx, acc[im][in][1] + by };
            float2 o1 = { acc[im][in][2] + bx, acc[im][in][3] + by };
            *reinterpret_cast<float2*>(Yb + (size_t)m * DOo + n) = o0;
            *reinterpret_cast<float2*>(Yb + (size_t)(m + 8) * DOo + n) = o1;
        }
    }
#undef LOAD_STAGE
}

// ================= gather-reduce + ReLU (half-batch group) =================
__global__ __launch_bounds__(128) void k_gather(float* __restrict__ out, int b_base) {
    const int r = b_base * Ss + blockIdx.x;
    const int b = r >> 11;
    const int o = threadIdx.x * 2;     // 0..254
    const int beg = g_offs[r];
    const int end = g_offs[r + 1];
    const float* Yb = g_y + (size_t)b * Ll * Ss * DOo;

    float2 a0 = {0.f, 0.f}, a1 = {0.f, 0.f}, a2 = {0.f, 0.f}, a3 = {0.f, 0.f};
    int i = beg;
    for (; i + 3 < end; i += 4) {
        int p0 = __ldg(&g_perm[i]);
        int p1 = __ldg(&g_perm[i + 1]);
        int p2 = __ldg(&g_perm[i + 2]);
        int p3 = __ldg(&g_perm[i + 3]);
        float2 v0 = *reinterpret_cast<const float2*>(Yb + (size_t)p0 * DOo + o);
        float2 v1 = *reinterpret_cast<const float2*>(Yb + (size_t)p1 * DOo + o);
        float2 v2 = *reinterpret_cast<const float2*>(Yb + (size_t)p2 * DOo + o);
        float2 v3 = *reinterpret_cast<const float2*>(Yb + (size_t)p3 * DOo + o);
        a0.x += v0.x; a0.y += v0.y;
        a1.x += v1.x; a1.y += v1.y;
        a2.x += v2.x; a2.y += v2.y;
        a3.x += v3.x; a3.y += v3.y;
    }
    for (; i < end; i++) {
        float2 v = *reinterpret_cast<const float2*>(
            Yb + (size_t)__ldg(&g_perm[i]) * DOo + o);
        a0.x += v.x; a0.y += v.y;
    }
    float2 res;
    res.x = fmaxf((a0.x + a1.x) + (a2.x + a3.x), 0.f);
    res.y = fmaxf((a0.y + a1.y) + (a2.y + a3.y), 0.f);
    *reinterpret_cast<float2*>(out + (size_t)r * DOo + o) = res;
}

// ================= launch =================
extern "C" void kernel_launch(void* const* d_in, const int* in_sizes, int n_in,
                              void* d_out, int out_size) {
    const float* X    = (const float*)d_in[0];
    const int*   esrc = (const int*)d_in[1];
    const int*   etgt = (const int*)d_in[2];
    const int*   elab = (const int*)d_in[3];
    const float* W    = (const float*)d_in[4];
    const float* bias = (const float*)d_in[5];
    float* out = (float*)d_out;

    const int SMEM_BYTES = NSTAGE * STAGE_BYTES;   // 64 KB
    cudaFuncSetAttribute(k_gemm_mma, cudaFuncAttributeMaxDynamicSharedMemorySize, SMEM_BYTES);
    dim3 ggrid(Ss / 128, DOo / 128, 4 * Ll);       // 1024 CTAs per half

    if (g_streams_ok) {
        cudaEventRecord(g_ev0, 0);
        cudaStreamWaitEvent(g_s2, g_ev0, 0);

        // CSR build on side stream
        k_zero_deg<<<(Bb * Ss + 255) / 256, 256, 0, g_s2>>>();
        k_hist<<<(Bb * Ee + 255) / 256, 256, 0, g_s2>>>(etgt);
        k_scan<<<1, 1024, 0, g_s2>>>();
        k_fill<<<(Bb * Ee + 255) / 256, 256, 0, g_s2>>>(etgt, elab, esrc);

        // main stream: prep, then GEMM halves
        k_prep<<<(Bb * Ss * Dd + 255) / 256, 256>>>(X, W);
        k_gemm_mma<<<ggrid, 256, SMEM_BYTES>>>(bias, 0);     // batches 0-3
        cudaEventRecord(g_evH0, 0);
        k_gemm_mma<<<ggrid, 256, SMEM_BYTES>>>(bias, 4);     // batches 4-7
        cudaEventRecord(g_evH1, 0);

        // side stream: gather halves overlapping GEMM
        cudaStreamWaitEvent(g_s2, g_evH0, 0);
        k_gather<<<4 * Ss, 128, 0, g_s2>>>(out, 0);
        cudaStreamWaitEvent(g_s2, g_evH1, 0);
        k_gather<<<4 * Ss, 128, 0, g_s2>>>(out, 4);
        cudaEventRecord(g_ev1, g_s2);
        cudaStreamWaitEvent(0, g_ev1, 0);     // join
    } else {
        k_zero_deg<<<(Bb * Ss + 255) / 256, 256>>>();
        k_hist<<<(Bb * Ee + 255) / 256, 256>>>(etgt);
        k_scan<<<1, 1024>>>();
        k_fill<<<(Bb * Ee + 255) / 256, 256>>>(etgt, elab, esrc);
        k_prep<<<(Bb * Ss * Dd + 255) / 256, 256>>>(X, W);
        k_gemm_mma<<<ggrid, 256, SMEM_BYTES>>>(bias, 0);
        k_gemm_mma<<<ggrid, 256, SMEM_BYTES>>>(bias, 4);
        k_gather<<<4 * Ss, 128>>>(out, 0);
        k_gather<<<4 * Ss, 128>>>(out, 4);
    }
}

// round 10
// speedup vs baseline: 2.0275x; 1.1532x over previous
#include <cuda_runtime.h>
#include <cuda_fp16.h>
#include <cstdint>

#define Bb  8
#define Ss  2048
#define Dd  256
#define DOo 256
#define Ll  8
#define Ee  32768

// ---- static device scratch ----
__device__ __align__(128) __half g_y[(size_t)Bb * Ll * Ss * DOo];  // 64 MiB (fp16 Y)
__device__ __align__(128) __half g_xf[(size_t)Bb * Ss * Dd];       // 8 MiB
__device__ __align__(128) __half g_wf[(size_t)Ll * DOo * Dd];      // 1 MiB [l][n][k]
__device__ int g_deg[Bb * Ss];
__device__ int g_offs[Bb * Ss + 1];
__device__ int g_cursor[Bb * Ss];
__device__ int g_perm[Bb * Ee];                                    // l*Ss + s

// ---- streams + events, created once at process init (outside capture) ----
static cudaStream_t g_s2 = nullptr;
static cudaEvent_t g_ev0 = nullptr, g_ev1 = nullptr;
static cudaEvent_t g_evH0 = nullptr, g_evH1 = nullptr;
static bool g_streams_ok = false;
namespace {
struct _StreamInit {
    _StreamInit() {
        bool ok = true;
        ok &= (cudaStreamCreateWithFlags(&g_s2, cudaStreamNonBlocking) == cudaSuccess);
        ok &= (cudaEventCreateWithFlags(&g_ev0, cudaEventDisableTiming) == cudaSuccess);
        ok &= (cudaEventCreateWithFlags(&g_ev1, cudaEventDisableTiming) == cudaSuccess);
        ok &= (cudaEventCreateWithFlags(&g_evH0, cudaEventDisableTiming) == cudaSuccess);
        ok &= (cudaEventCreateWithFlags(&g_evH1, cudaEventDisableTiming) == cudaSuccess);
        g_streams_ok = ok;
    }
} _stream_init;
}

// ================= CSR-build kernels =================
__global__ void k_zero_deg() {
    int i = blockIdx.x * blockDim.x + threadIdx.x;
    if (i < Bb * Ss) g_deg[i] = 0;
}
__global__ void k_hist(const int* __restrict__ tgt) {
    int i = blockIdx.x * blockDim.x + threadIdx.x;
    if (i < Bb * Ee) {
        int b = i / Ee;
        atomicAdd(&g_deg[b * Ss + tgt[i]], 1);
    }
}
__global__ void k_scan() {   // 1024 threads, 16 rows each
    const int t = threadIdx.x;
    const int base = t * 16;
    int loc[16]; int sum = 0;
#pragma unroll
    for (int i = 0; i < 16; i++) { loc[i] = sum; sum += g_deg[base + i]; }
    int lane = t & 31, warp = t >> 5;
    int v = sum;
#pragma unroll
    for (int o = 1; o < 32; o <<= 1) {
        int u = __shfl_up_sync(0xFFFFFFFF, v, o);
        if (lane >= o) v += u;
    }
    __shared__ int wsum[32];
    if (lane == 31) wsum[warp] = v;
    __syncthreads();
    if (warp == 0) {
        int w = wsum[lane];
#pragma unroll
        for (int o = 1; o < 32; o <<= 1) {
            int u = __shfl_up_sync(0xFFFFFFFF, w, o);
            if (lane >= o) w += u;
        }
        wsum[lane] = w;
    }
    __syncthreads();
    int pre = v - sum + (warp ? wsum[warp - 1] : 0);
#pragma unroll
    for (int i = 0; i < 16; i++) {
        int o = pre + loc[i];
        g_offs[base + i]   = o;
        g_cursor[base + i] = o;
    }
    if (t == 1023) g_offs[Bb * Ss] = wsum[31];
}
__global__ void k_fill(const int* __restrict__ tgt, const int* __restrict__ lab,
                       const int* __restrict__ src) {
    int i = blockIdx.x * blockDim.x + threadIdx.x;
    if (i < Bb * Ee) {
        int b = i / Ee;
        int pos = atomicAdd(&g_cursor[b * Ss + tgt[i]], 1);
        g_perm[pos] = lab[i] * Ss + src[i];
    }
}

// ================= prep: fp32 -> fp16 casts =================
__global__ void k_prep(const float* __restrict__ X, const float* __restrict__ W) {
    int i = blockIdx.x * blockDim.x + threadIdx.x;
    if (i < Bb * Ss * Dd) g_xf[i] = __float2half(X[i]);
    if (i < Ll * Dd * DOo) {
        int l = i / (Dd * DOo);
        int r = i - l * (Dd * DOo);
        int k = r >> 8;
        int n = r & 255;
        g_wf[((size_t)l * DOo + n) * Dd + k] = __float2half(W[i]);
    }
}

// ================= fp16 mma.sync GEMM (half-batch group) =================
__device__ __forceinline__ uint32_t s2u(const void* p) {
    uint32_t a;
    asm("{ .reg .u64 t; cvta.to.shared.u64 t, %1; cvt.u32.u64 %0, t; }" : "=r"(a) : "l"(p));
    return a;
}
__device__ __forceinline__ void cp16(uint32_t sa, const void* ga) {
    asm volatile("cp.async.cg.shared.global [%0], [%1], 16;" :: "r"(sa), "l"(ga));
}
__device__ __forceinline__ void ldmx4(uint32_t* r, uint32_t addr) {
    asm volatile("ldmatrix.sync.aligned.m8n8.x4.shared.b16 {%0,%1,%2,%3}, [%4];"
                 : "=r"(r[0]), "=r"(r[1]), "=r"(r[2]), "=r"(r[3]) : "r"(addr));
}
__device__ __forceinline__ void mma16816(float* c, const uint32_t* a,
                                         uint32_t b0, uint32_t b1) {
    asm volatile(
        "mma.sync.aligned.m16n8k16.row.col.f32.f16.f16.f32 "
        "{%0,%1,%2,%3}, {%4,%5,%6,%7}, {%8,%9}, {%0,%1,%2,%3};"
        : "+f"(c[0]), "+f"(c[1]), "+f"(c[2]), "+f"(c[3])
        : "r"(a[0]), "r"(a[1]), "r"(a[2]), "r"(a[3]), "r"(b0), "r"(b1));
}

#define STAGE_BYTES 16384      // 2 tiles x 8KB (A, B), 128 rows x 64B each
#define OFF_A 0
#define OFF_B 8192
#define NSTAGE 4

// grid: (Ss/128, DOo/128, 4*Ll); batch = b_base + z>>3, label = z&7
__global__ __launch_bounds__(256, 2) void k_gemm_mma(const float* __restrict__ bias,
                                                     int b_base) {
    extern __shared__ char smem[];
    const uint32_t sbase = s2u(smem);          // 4 stages x 16KB

    const int tid = threadIdx.x;
    const int lane = tid & 31;
    const int wid = tid >> 5;
    const int warp_m = wid & 1;                // 2 x 64 rows
    const int warp_n = wid >> 1;               // 4 x 32 cols
    const int z = blockIdx.z;
    const int b = b_base + (z >> 3);
    const int l = z & 7;
    const int bl = b * Ll + l;
    const int m0 = blockIdx.x * 128;
    const int n0 = blockIdx.y * 128;

    const __half* Ag = g_xf + ((size_t)(b * Ss) + m0) * Dd;
    const __half* Bg = g_wf + ((size_t)l * DOo + n0) * Dd;

    const int u_row0 = tid >> 2,          u_u0 = tid & 3;
    const int u_row1 = (tid + 256) >> 2,  u_u1 = (tid + 256) & 3;
    const uint32_t so0 = (uint32_t)(u_row0 * 64 + ((u_u0 ^ ((u_row0 >> 1) & 3)) << 4));
    const uint32_t so1 = (uint32_t)(u_row1 * 64 + ((u_u1 ^ ((u_row1 >> 1) & 3)) << 4));

#define LOAD_STAGE(st, it) do {                                                     \
    int koff = (it) * 32;                                                           \
    uint32_t s0 = sbase + (st) * STAGE_BYTES;                                       \
    cp16(s0 + OFF_A + so0, Ag + (size_t)u_row0 * Dd + koff + u_u0 * 8);             \
    cp16(s0 + OFF_A + so1, Ag + (size_t)u_row1 * Dd + koff + u_u1 * 8);             \
    cp16(s0 + OFF_B + so0, Bg + (size_t)u_row0 * Dd + koff + u_u0 * 8);             \
    cp16(s0 + OFF_B + so1, Bg + (size_t)u_row1 * Dd + koff + u_u1 * 8);             \
} while (0)

    float acc[4][4][4];
#pragma unroll
    for (int i = 0; i < 4; i++)
#pragma unroll
        for (int j = 0; j < 4; j++)
#pragma unroll
            for (int q = 0; q < 4; q++) acc[i][j][q] = 0.f;

    LOAD_STAGE(0, 0);
    asm volatile("cp.async.commit_group;" ::: "memory");
    LOAD_STAGE(1, 1);
    asm volatile("cp.async.commit_group;" ::: "memory");
    LOAD_STAGE(2, 2);
    asm volatile("cp.async.commit_group;" ::: "memory");

    const int arow_base = warp_m * 64 + (lane & 15);
    const int nrow_base = warp_n * 32 + ((lane >> 4) << 3) + (lane & 7);

    const int NIT = Dd / 32;   // 8
    for (int it = 0; it < NIT; it++) {
        asm volatile("cp.async.wait_group 2;" ::: "memory");
        __syncthreads();
        if (it + 3 < NIT) {
            int st = (it + 3) % NSTAGE;
            LOAD_STAGE(st, it + 3);
        }
        asm volatile("cp.async.commit_group;" ::: "memory");

        const uint32_t stg = sbase + (it % NSTAGE) * STAGE_BYTES;
#pragma unroll
        for (int ks = 0; ks < 2; ks++) {
            const int akk = ks * 16 + (lane >> 4) * 8;
            const int bkk = ks * 16 + ((lane >> 3) & 1) * 8;

            uint32_t af[4][4], bf[2][4];
#pragma unroll
            for (int im = 0; im < 4; im++) {
                int row = arow_base + im * 16;
                uint32_t off = row * 64 + ((((akk >> 3)) ^ ((row >> 1) & 3)) << 4);
                ldmx4(af[im], stg + OFF_A + off);
            }
#pragma unroll
            for (int ib = 0; ib < 2; ib++) {
                int row = nrow_base + ib * 16;
                uint32_t off = row * 64 + ((((bkk >> 3)) ^ ((row >> 1) & 3)) << 4);
                ldmx4(bf[ib], stg + OFF_B + off);
            }
#pragma unroll
            for (int im = 0; im < 4; im++)
#pragma unroll
                for (int in = 0; in < 4; in++)
                    mma16816(acc[im][in], af[im],
                             bf[in >> 1][(in & 1) * 2], bf[in >> 1][(in & 1) * 2 + 1]);
        }
    }

    // epilogue: Y = half(acc + bias)
    __half* Yb = g_y + (size_t)bl * Ss * DOo;
    const float* bp = bias + l * DOo;
#pragma unroll
    for (int im = 0; im < 4; im++) {
        int m = m0 + warp_m * 64 + im * 16 + (lane >> 2);
#pragma unroll
        for (int in = 0; in < 4; in++) {
            int n = n0 + warp_n * 32 + in * 8 + 2 * (lane & 3);
            float bx = bp[n], by = bp[n + 1];
            float2 f0 = { acc[im][in][0] + bx, acc[im][in][1] + by };
            float2 f1 = { acc[im][in][2] + bx, acc[im][in][3] + by };
            __half2 h0 = __float22half2_rn(f0);
            __half2 h1 = __float22half2_rn(f1);
            *reinterpret_cast<__half2*>(Yb + (size_t)m * DOo + n) = h0;
            *reinterpret_cast<__half2*>(Yb + (size_t)(m + 8) * DOo + n) = h1;
        }
    }
#undef LOAD_STAGE
}

// ================= gather-reduce + ReLU (half-batch group, fp16 Y) =============
__global__ __launch_bounds__(128) void k_gather(float* __restrict__ out, int b_base) {
    const int r = b_base * Ss + blockIdx.x;
    const int b = r >> 11;
    const int o = threadIdx.x * 2;     // 0..254
    const int beg = g_offs[r];
    const int end = g_offs[r + 1];
    const __half* Yb = g_y + (size_t)b * Ll * Ss * DOo;

    float2 a0 = {0.f, 0.f}, a1 = {0.f, 0.f}, a2 = {0.f, 0.f}, a3 = {0.f, 0.f};
    int i = beg;
    for (; i + 3 < end; i += 4) {
        int p0 = __ldg(&g_perm[i]);
        int p1 = __ldg(&g_perm[i + 1]);
        int p2 = __ldg(&g_perm[i + 2]);
        int p3 = __ldg(&g_perm[i + 3]);
        float2 v0 = __half22float2(*reinterpret_cast<const __half2*>(Yb + (size_t)p0 * DOo + o));
        float2 v1 = __half22float2(*reinterpret_cast<const __half2*>(Yb + (size_t)p1 * DOo + o));
        float2 v2 = __half22float2(*reinterpret_cast<const __half2*>(Yb + (size_t)p2 * DOo + o));
        float2 v3 = __half22float2(*reinterpret_cast<const __half2*>(Yb + (size_t)p3 * DOo + o));
        a0.x += v0.x; a0.y += v0.y;
        a1.x += v1.x; a1.y += v1.y;
        a2.x += v2.x; a2.y += v2.y;
        a3.x += v3.x; a3.y += v3.y;
    }
    for (; i < end; i++) {
        float2 v = __half22float2(*reinterpret_cast<const __half2*>(
            Yb + (size_t)__ldg(&g_perm[i]) * DOo + o));
        a0.x += v.x; a0.y += v.y;
    }
    float2 res;
    res.x = fmaxf((a0.x + a1.x) + (a2.x + a3.x), 0.f);
    res.y = fmaxf((a0.y + a1.y) + (a2.y + a3.y), 0.f);
    *reinterpret_cast<float2*>(out + (size_t)r * DOo + o) = res;
}

// ================= launch =================
extern "C" void kernel_launch(void* const* d_in, const int* in_sizes, int n_in,
                              void* d_out, int out_size) {
    const float* X    = (const float*)d_in[0];
    const int*   esrc = (const int*)d_in[1];
    const int*   etgt = (const int*)d_in[2];
    const int*   elab = (const int*)d_in[3];
    const float* W    = (const float*)d_in[4];
    const float* bias = (const float*)d_in[5];
    float* out = (float*)d_out;

    const int SMEM_BYTES = NSTAGE * STAGE_BYTES;   // 64 KB
    cudaFuncSetAttribute(k_gemm_mma, cudaFuncAttributeMaxDynamicSharedMemorySize, SMEM_BYTES);
    dim3 ggrid(Ss / 128, DOo / 128, 4 * Ll);       // 1024 CTAs per half

    if (g_streams_ok) {
        cudaEventRecord(g_ev0, 0);
        cudaStreamWaitEvent(g_s2, g_ev0, 0);

        // CSR build on side stream
        k_zero_deg<<<(Bb * Ss + 255) / 256, 256, 0, g_s2>>>();
        k_hist<<<(Bb * Ee + 255) / 256, 256, 0, g_s2>>>(etgt);
        k_scan<<<1, 1024, 0, g_s2>>>();
        k_fill<<<(Bb * Ee + 255) / 256, 256, 0, g_s2>>>(etgt, elab, esrc);

        // main stream: prep, then GEMM halves
        k_prep<<<(Bb * Ss * Dd + 255) / 256, 256>>>(X, W);
        k_gemm_mma<<<ggrid, 256, SMEM_BYTES>>>(bias, 0);     // batches 0-3
        cudaEventRecord(g_evH0, 0);
        k_gemm_mma<<<ggrid, 256, SMEM_BYTES>>>(bias, 4);     // batches 4-7
        cudaEventRecord(g_evH1, 0);

        // side stream: gather halves overlapping GEMM
        cudaStreamWaitEvent(g_s2, g_evH0, 0);
        k_gather<<<4 * Ss, 128, 0, g_s2>>>(out, 0);
        cudaStreamWaitEvent(g_s2, g_evH1, 0);
        k_gather<<<4 * Ss, 128, 0, g_s2>>>(out, 4);
        cudaEventRecord(g_ev1, g_s2);
        cudaStreamWaitEvent(0, g_ev1, 0);     // join
    } else {
        k_zero_deg<<<(Bb * Ss + 255) / 256, 256>>>();
        k_hist<<<(Bb * Ee + 255) / 256, 256>>>(etgt);
        k_scan<<<1, 1024>>>();
        k_fill<<<(Bb * Ee + 255) / 256, 256>>>(etgt, elab, esrc);
        k_prep<<<(Bb * Ss * Dd + 255) / 256, 256>>>(X, W);
        k_gemm_mma<<<ggrid, 256, SMEM_BYTES>>>(bias, 0);
        k_gemm_mma<<<ggrid, 256, SMEM_BYTES>>>(bias, 4);
        k_gather<<<4 * Ss, 128>>>(out, 0);
        k_gather<<<4 * Ss, 128>>>(out, 4);
    }
}

// round 11
// speedup vs baseline: 2.0330x; 1.0028x over previous
#include <cuda_runtime.h>
#include <cuda_fp16.h>
#include <cstdint>

#define Bb  8
#define Ss  2048
#define Dd  256
#define DOo 256
#define Ll  8
#define Ee  32768

// ---- static device scratch ----
__device__ __align__(128) __half g_y[(size_t)Bb * Ll * Ss * DOo];  // 64 MiB (fp16 Y)
__device__ __align__(128) __half g_xf[(size_t)Bb * Ss * Dd];       // 8 MiB
__device__ __align__(128) __half g_wf[(size_t)Ll * DOo * Dd];      // 1 MiB [l][n][k]
__device__ int g_deg[Bb * Ss];
__device__ int g_offs[Bb * Ss + 1];
__device__ int g_cursor[Bb * Ss];
__device__ int g_perm[Bb * Ee];                                    // l*Ss + s

// ---- streams + events, created once at process init (outside capture) ----
static cudaStream_t g_s2 = nullptr;
static cudaEvent_t g_ev0 = nullptr, g_ev1 = nullptr;
static cudaEvent_t g_evH0 = nullptr, g_evH1 = nullptr, g_evP1 = nullptr;
static bool g_streams_ok = false;
namespace {
struct _StreamInit {
    _StreamInit() {
        bool ok = true;
        ok &= (cudaStreamCreateWithFlags(&g_s2, cudaStreamNonBlocking) == cudaSuccess);
        ok &= (cudaEventCreateWithFlags(&g_ev0, cudaEventDisableTiming) == cudaSuccess);
        ok &= (cudaEventCreateWithFlags(&g_ev1, cudaEventDisableTiming) == cudaSuccess);
        ok &= (cudaEventCreateWithFlags(&g_evH0, cudaEventDisableTiming) == cudaSuccess);
        ok &= (cudaEventCreateWithFlags(&g_evH1, cudaEventDisableTiming) == cudaSuccess);
        ok &= (cudaEventCreateWithFlags(&g_evP1, cudaEventDisableTiming) == cudaSuccess);
        g_streams_ok = ok;
    }
} _stream_init;
}

// ================= CSR-build kernels =================
__global__ void k_zero_deg() {
    int i = blockIdx.x * blockDim.x + threadIdx.x;
    if (i < Bb * Ss) g_deg[i] = 0;
}
__global__ void k_hist(const int* __restrict__ tgt) {
    int i = blockIdx.x * blockDim.x + threadIdx.x;
    if (i < Bb * Ee) {
        int b = i / Ee;
        atomicAdd(&g_deg[b * Ss + tgt[i]], 1);
    }
}
__global__ void k_scan() {   // 1024 threads, 16 rows each
    const int t = threadIdx.x;
    const int base = t * 16;
    int loc[16]; int sum = 0;
#pragma unroll
    for (int i = 0; i < 16; i++) { loc[i] = sum; sum += g_deg[base + i]; }
    int lane = t & 31, warp = t >> 5;
    int v = sum;
#pragma unroll
    for (int o = 1; o < 32; o <<= 1) {
        int u = __shfl_up_sync(0xFFFFFFFF, v, o);
        if (lane >= o) v += u;
    }
    __shared__ int wsum[32];
    if (lane == 31) wsum[warp] = v;
    __syncthreads();
    if (warp == 0) {
        int w = wsum[lane];
#pragma unroll
        for (int o = 1; o < 32; o <<= 1) {
            int u = __shfl_up_sync(0xFFFFFFFF, w, o);
            if (lane >= o) w += u;
        }
        wsum[lane] = w;
    }
    __syncthreads();
    int pre = v - sum + (warp ? wsum[warp - 1] : 0);
#pragma unroll
    for (int i = 0; i < 16; i++) {
        int o = pre + loc[i];
        g_offs[base + i]   = o;
        g_cursor[base + i] = o;
    }
    if (t == 1023) g_offs[Bb * Ss] = wsum[31];
}
__global__ void k_fill(const int* __restrict__ tgt, const int* __restrict__ lab,
                       const int* __restrict__ src) {
    int i = blockIdx.x * blockDim.x + threadIdx.x;
    if (i < Bb * Ee) {
        int b = i / Ee;
        int pos = atomicAdd(&g_cursor[b * Ss + tgt[i]], 1);
        g_perm[pos] = lab[i] * Ss + src[i];
    }
}

// ================= prep kernels =================
// prep0: W cast+transpose + X cast for batches 0-3
__global__ void k_prep0(const float* __restrict__ X, const float* __restrict__ W) {
    int i = blockIdx.x * blockDim.x + threadIdx.x;
    if (i < 4 * Ss * Dd) g_xf[i] = __float2half(X[i]);
    if (i < Ll * Dd * DOo) {
        int l = i / (Dd * DOo);
        int r = i - l * (Dd * DOo);
        int k = r >> 8;
        int n = r & 255;
        g_wf[((size_t)l * DOo + n) * Dd + k] = __float2half(W[i]);
    }
}
// prep1: X cast for batches 4-7 (runs on side stream under gemmH0)
__global__ void k_prep1(const float* __restrict__ X) {
    int i = blockIdx.x * blockDim.x + threadIdx.x;
    if (i < 4 * Ss * Dd) {
        int j = 4 * Ss * Dd + i;
        g_xf[j] = __float2half(X[j]);
    }
}

// ================= fp16 mma.sync GEMM (half-batch group) =================
__device__ __forceinline__ uint32_t s2u(const void* p) {
    uint32_t a;
    asm("{ .reg .u64 t; cvta.to.shared.u64 t, %1; cvt.u32.u64 %0, t; }" : "=r"(a) : "l"(p));
    return a;
}
__device__ __forceinline__ void cp16(uint32_t sa, const void* ga) {
    asm volatile("cp.async.cg.shared.global [%0], [%1], 16;" :: "r"(sa), "l"(ga));
}
__device__ __forceinline__ void ldmx4(uint32_t* r, uint32_t addr) {
    asm volatile("ldmatrix.sync.aligned.m8n8.x4.shared.b16 {%0,%1,%2,%3}, [%4];"
                 : "=r"(r[0]), "=r"(r[1]), "=r"(r[2]), "=r"(r[3]) : "r"(addr));
}
__device__ __forceinline__ void mma16816(float* c, const uint32_t* a,
                                         uint32_t b0, uint32_t b1) {
    asm volatile(
        "mma.sync.aligned.m16n8k16.row.col.f32.f16.f16.f32 "
        "{%0,%1,%2,%3}, {%4,%5,%6,%7}, {%8,%9}, {%0,%1,%2,%3};"
        : "+f"(c[0]), "+f"(c[1]), "+f"(c[2]), "+f"(c[3])
        : "r"(a[0]), "r"(a[1]), "r"(a[2]), "r"(a[3]), "r"(b0), "r"(b1));
}

#define STAGE_BYTES 16384      // 2 tiles x 8KB (A, B), 128 rows x 64B each
#define OFF_A 0
#define OFF_B 8192
#define NSTAGE 4

// grid: (Ss/128, DOo/128, 4*Ll); batch = b_base + z>>3, label = z&7
__global__ __launch_bounds__(256, 2) void k_gemm_mma(const float* __restrict__ bias,
                                                     int b_base) {
    extern __shared__ char smem[];
    const uint32_t sbase = s2u(smem);          // 4 stages x 16KB

    const int tid = threadIdx.x;
    const int lane = tid & 31;
    const int wid = tid >> 5;
    const int warp_m = wid & 1;                // 2 x 64 rows
    const int warp_n = wid >> 1;               // 4 x 32 cols
    const int z = blockIdx.z;
    const int b = b_base + (z >> 3);
    const int l = z & 7;
    const int bl = b * Ll + l;
    const int m0 = blockIdx.x * 128;
    const int n0 = blockIdx.y * 128;

    const __half* Ag = g_xf + ((size_t)(b * Ss) + m0) * Dd;
    const __half* Bg = g_wf + ((size_t)l * DOo + n0) * Dd;

    const int u_row0 = tid >> 2,          u_u0 = tid & 3;
    const int u_row1 = (tid + 256) >> 2,  u_u1 = (tid + 256) & 3;
    const uint32_t so0 = (uint32_t)(u_row0 * 64 + ((u_u0 ^ ((u_row0 >> 1) & 3)) << 4));
    const uint32_t so1 = (uint32_t)(u_row1 * 64 + ((u_u1 ^ ((u_row1 >> 1) & 3)) << 4));

#define LOAD_STAGE(st, it) do {                                                     \
    int koff = (it) * 32;                                                           \
    uint32_t s0 = sbase + (st) * STAGE_BYTES;                                       \
    cp16(s0 + OFF_A + so0, Ag + (size_t)u_row0 * Dd + koff + u_u0 * 8);             \
    cp16(s0 + OFF_A + so1, Ag + (size_t)u_row1 * Dd + koff + u_u1 * 8);             \
    cp16(s0 + OFF_B + so0, Bg + (size_t)u_row0 * Dd + koff + u_u0 * 8);             \
    cp16(s0 + OFF_B + so1, Bg + (size_t)u_row1 * Dd + koff + u_u1 * 8);             \
} while (0)

    float acc[4][4][4];
#pragma unroll
    for (int i = 0; i < 4; i++)
#pragma unroll
        for (int j = 0; j < 4; j++)
#pragma unroll
            for (int q = 0; q < 4; q++) acc[i][j][q] = 0.f;

    LOAD_STAGE(0, 0);
    asm volatile("cp.async.commit_group;" ::: "memory");
    LOAD_STAGE(1, 1);
    asm volatile("cp.async.commit_group;" ::: "memory");
    LOAD_STAGE(2, 2);
    asm volatile("cp.async.commit_group;" ::: "memory");

    const int arow_base = warp_m * 64 + (lane & 15);
    const int nrow_base = warp_n * 32 + ((lane >> 4) << 3) + (lane & 7);

    const int NIT = Dd / 32;   // 8
    for (int it = 0; it < NIT; it++) {
        asm volatile("cp.async.wait_group 2;" ::: "memory");
        __syncthreads();
        if (it + 3 < NIT) {
            int st = (it + 3) % NSTAGE;
            LOAD_STAGE(st, it + 3);
        }
        asm volatile("cp.async.commit_group;" ::: "memory");

        const uint32_t stg = sbase + (it % NSTAGE) * STAGE_BYTES;
#pragma unroll
        for (int ks = 0; ks < 2; ks++) {
            const int akk = ks * 16 + (lane >> 4) * 8;
            const int bkk = ks * 16 + ((lane >> 3) & 1) * 8;

            uint32_t af[4][4], bf[2][4];
#pragma unroll
            for (int im = 0; im < 4; im++) {
                int row = arow_base + im * 16;
                uint32_t off = row * 64 + ((((akk >> 3)) ^ ((row >> 1) & 3)) << 4);
                ldmx4(af[im], stg + OFF_A + off);
            }
#pragma unroll
            for (int ib = 0; ib < 2; ib++) {
                int row = nrow_base + ib * 16;
                uint32_t off = row * 64 + ((((bkk >> 3)) ^ ((row >> 1) & 3)) << 4);
                ldmx4(bf[ib], stg + OFF_B + off);
            }
#pragma unroll
            for (int im = 0; im < 4; im++)
#pragma unroll
                for (int in = 0; in < 4; in++)
                    mma16816(acc[im][in], af[im],
                             bf[in >> 1][(in & 1) * 2], bf[in >> 1][(in & 1) * 2 + 1]);
        }
    }

    // epilogue: Y = half(acc + bias)
    __half* Yb = g_y + (size_t)bl * Ss * DOo;
    const float* bp = bias + l * DOo;
#pragma unroll
    for (int im = 0; im < 4; im++) {
        int m = m0 + warp_m * 64 + im * 16 + (lane >> 2);
#pragma unroll
        for (int in = 0; in < 4; in++) {
            int n = n0 + warp_n * 32 + in * 8 + 2 * (lane & 3);
            float bx = bp[n], by = bp[n + 1];
            float2 f0 = { acc[im][in][0] + bx, acc[im][in][1] + by };
            float2 f1 = { acc[im][in][2] + bx, acc[im][in][3] + by };
            __half2 h0 = __float22half2_rn(f0);
            __half2 h1 = __float22half2_rn(f1);
            *reinterpret_cast<__half2*>(Yb + (size_t)m * DOo + n) = h0;
            *reinterpret_cast<__half2*>(Yb + (size_t)(m + 8) * DOo + n) = h1;
        }
    }
#undef LOAD_STAGE
}

// ================= gather-reduce + ReLU: one warp per row, LDG.128 ==============
// block = 256 threads = 8 warps = 8 rows; grid = 4*Ss/8 per half
__global__ __launch_bounds__(256) void k_gather(float* __restrict__ out, int b_base) {
    const int warp = threadIdx.x >> 5;
    const int lane = threadIdx.x & 31;
    const int r = b_base * Ss + blockIdx.x * 8 + warp;
    const int b = r >> 11;
    const int co = lane * 8;                 // 8 halves per lane
    const int beg = g_offs[r];
    const int end = g_offs[r + 1];
    const __half* Yb = g_y + (size_t)b * Ll * Ss * DOo;

    float acc[8] = {0.f, 0.f, 0.f, 0.f, 0.f, 0.f, 0.f, 0.f};

#define ACC8(v) do {                                                             \
    float2 t0 = __half22float2(*reinterpret_cast<const __half2*>(&(v).x));       \
    float2 t1 = __half22float2(*reinterpret_cast<const __half2*>(&(v).y));       \
    float2 t2 = __half22float2(*reinterpret_cast<const __half2*>(&(v).z));       \
    float2 t3 = __half22float2(*reinterpret_cast<const __half2*>(&(v).w));       \
    acc[0] += t0.x; acc[1] += t0.y; acc[2] += t1.x; acc[3] += t1.y;              \
    acc[4] += t2.x; acc[5] += t2.y; acc[6] += t3.x; acc[7] += t3.y;              \
} while (0)

    int i = beg;
    for (; i + 3 < end; i += 4) {
        int p0 = __ldg(&g_perm[i]);
        int p1 = __ldg(&g_perm[i + 1]);
        int p2 = __ldg(&g_perm[i + 2]);
        int p3 = __ldg(&g_perm[i + 3]);
        uint4 v0 = *reinterpret_cast<const uint4*>(Yb + (size_t)p0 * DOo + co);
        uint4 v1 = *reinterpret_cast<const uint4*>(Yb + (size_t)p1 * DOo + co);
        uint4 v2 = *reinterpret_cast<const uint4*>(Yb + (size_t)p2 * DOo + co);
        uint4 v3 = *reinterpret_cast<const uint4*>(Yb + (size_t)p3 * DOo + co);
        ACC8(v0); ACC8(v1); ACC8(v2); ACC8(v3);
    }
    for (; i < end; i++) {
        uint4 v = *reinterpret_cast<const uint4*>(
            Yb + (size_t)__ldg(&g_perm[i]) * DOo + co);
        ACC8(v);
    }
#undef ACC8

    float* op = out + (size_t)r * DOo + co;
    float4 o0 = { fmaxf(acc[0], 0.f), fmaxf(acc[1], 0.f),
                  fmaxf(acc[2], 0.f), fmaxf(acc[3], 0.f) };
    float4 o1 = { fmaxf(acc[4], 0.f), fmaxf(acc[5], 0.f),
                  fmaxf(acc[6], 0.f), fmaxf(acc[7], 0.f) };
    *reinterpret_cast<float4*>(op)     = o0;
    *reinterpret_cast<float4*>(op + 4) = o1;
}

// ================= launch =================
extern "C" void kernel_launch(void* const* d_in, const int* in_sizes, int n_in,
                              void* d_out, int out_size) {
    const float* X    = (const float*)d_in[0];
    const int*   esrc = (const int*)d_in[1];
    const int*   etgt = (const int*)d_in[2];
    const int*   elab = (const int*)d_in[3];
    const float* W    = (const float*)d_in[4];
    const float* bias = (const float*)d_in[5];
    float* out = (float*)d_out;

    const int SMEM_BYTES = NSTAGE * STAGE_BYTES;   // 64 KB
    cudaFuncSetAttribute(k_gemm_mma, cudaFuncAttributeMaxDynamicSharedMemorySize, SMEM_BYTES);
    dim3 ggrid(Ss / 128, DOo / 128, 4 * Ll);       // 1024 CTAs per half
    const int PREP_TH = 4 * Ss * Dd;               // 2M threads per X half

    if (g_streams_ok) {
        cudaEventRecord(g_ev0, 0);
        cudaStreamWaitEvent(g_s2, g_ev0, 0);

        // launches 1,2 (side): CSR start
        k_zero_deg<<<(Bb * Ss + 255) / 256, 256, 0, g_s2>>>();
        k_hist<<<(Bb * Ee + 255) / 256, 256, 0, g_s2>>>(etgt);

        // launch 3 (main): prep half0 + W;  launch 4 (main): gemmH0  <- profiled slot
        k_prep0<<<(PREP_TH + 255) / 256, 256>>>(X, W);
        k_gemm_mma<<<ggrid, 256, SMEM_BYTES>>>(bias, 0);     // batches 0-3
        cudaEventRecord(g_evH0, 0);

        // side: prep half1 (under gemmH0), then CSR finish
        k_prep1<<<(PREP_TH + 255) / 256, 256, 0, g_s2>>>(X);
        cudaEventRecord(g_evP1, g_s2);
        k_scan<<<1, 1024, 0, g_s2>>>();
        k_fill<<<(Bb * Ee + 255) / 256, 256, 0, g_s2>>>(etgt, elab, esrc);

        // main: gemmH1 after prep1
        cudaStreamWaitEvent(0, g_evP1, 0);
        k_gemm_mma<<<ggrid, 256, SMEM_BYTES>>>(bias, 4);     // batches 4-7
        cudaEventRecord(g_evH1, 0);

        // side: gathers (after CSR by stream order, after GEMMs by events)
        cudaStreamWaitEvent(g_s2, g_evH0, 0);
        k_gather<<<4 * Ss / 8, 256, 0, g_s2>>>(out, 0);
        cudaStreamWaitEvent(g_s2, g_evH1, 0);
        k_gather<<<4 * Ss / 8, 256, 0, g_s2>>>(out, 4);
        cudaEventRecord(g_ev1, g_s2);
        cudaStreamWaitEvent(0, g_ev1, 0);     // join
    } else {
        k_zero_deg<<<(Bb * Ss + 255) / 256, 256>>>();
        k_hist<<<(Bb * Ee + 255) / 256, 256>>>(etgt);
        k_scan<<<1, 1024>>>();
        k_fill<<<(Bb * Ee + 255) / 256, 256>>>(etgt, elab, esrc);
        k_prep0<<<(PREP_TH + 255) / 256, 256>>>(X, W);
        k_prep1<<<(PREP_TH + 255) / 256, 256>>>(X);
        k_gemm_mma<<<ggrid, 256, SMEM_BYTES>>>(bias, 0);
        k_gemm_mma<<<ggrid, 256, SMEM_BYTES>>>(bias, 4);
        k_gather<<<4 * Ss / 8, 256>>>(out, 0);
        k_gather<<<4 * Ss / 8, 256>>>(out, 4);
    }
}